// round 1
// baseline (speedup 1.0000x reference)
#include <cuda_runtime.h>
#include <math.h>

// Problem constants (fixed by the dataset):
//   q,k,v: (B=2, S=2048, H=16, C=64) f32
//   bias : (B, H, S, S) f32
//   m    : (B, S) int32, sorted ascending per batch (segment ids 0..3)
//   out  : (B, S, H, C) f32
namespace {

constexpr int B_   = 2;
constexpr int SEQ  = 2048;
constexpr int H_   = 16;
constexpr int C_   = 64;
constexpr int BQ   = 64;   // q-tile rows
constexpr int BK   = 64;   // k-tile cols
constexpr int STRIDE = 68; // smem row stride (floats), 16B-aligned, limits conflicts to 2-way
constexpr float SM_SCALE = 0.125f; // 1/sqrt(64)

__global__ void __launch_bounds__(256)
attn_fa_kernel(const float* __restrict__ q,
               const float* __restrict__ k,
               const float* __restrict__ v,
               const float* __restrict__ bias,
               const int*   __restrict__ m,
               float* __restrict__ out)
{
    extern __shared__ float smem[];
    float* Qs = smem;                   // BQ x STRIDE
    float* Ks = Qs + BQ * STRIDE;       // BK x STRIDE
    float* Vs = Ks + BK * STRIDE;       // BK x STRIDE
    float* Ps = Vs + BK * STRIDE;       // BQ x STRIDE
    int*   mks = (int*)(Ps + BQ * STRIDE); // BK ints

    const int qt = blockIdx.x;
    const int h  = blockIdx.y;
    const int b  = blockIdx.z;
    const int q0 = qt * BQ;

    const int tid = threadIdx.x;
    const int tx  = tid & 15;   // 16 col-groups
    const int ty  = tid >> 4;   // 16 row-groups

    const size_t qkv_base = ((size_t)(b * SEQ) * H_ + h) * C_;
    const float* qp = q + qkv_base + (size_t)q0 * H_ * C_;
    const float* kp = k + qkv_base;
    const float* vp = v + qkv_base;
    const float* bp = bias + ((size_t)(b * H_ + h)) * SEQ * SEQ;
    const int*   mb = m + b * SEQ;

    // ---- load Q tile (64x64 f32) into smem, float4 coalesced ----
    #pragma unroll
    for (int i = 0; i < 4; i++) {
        int idx = tid + i * 256;        // float4 index within tile
        int r   = idx >> 4;             // 16 float4 per 64-float row
        int c4  = idx & 15;
        *(float4*)(Qs + r * STRIDE + c4 * 4) =
            *(const float4*)(qp + (size_t)r * H_ * C_ + c4 * 4);
    }

    // segment ids of my 4 q-rows
    int mq[4];
    #pragma unroll
    for (int i = 0; i < 4; i++) mq[i] = mb[q0 + ty + 16 * i];
    const int mq_lo = mb[q0];           // sorted => min over tile

    // lower_bound: first key index with m >= mq_lo. All earlier k-tiles are
    // fully masked (m_k < mq_lo <= every mq  => never equal), skip them.
    int lo = 0, hi = q0;
    while (lo < hi) {
        int mid = (lo + hi) >> 1;
        if (mb[mid] < mq_lo) lo = mid + 1; else hi = mid;
    }
    const int kt_start = lo >> 6;

    float mi[4], li[4], o[4][4];
    #pragma unroll
    for (int i = 0; i < 4; i++) {
        mi[i] = -1e30f; li[i] = 0.f;
        #pragma unroll
        for (int j = 0; j < 4; j++) o[i][j] = 0.f;
    }

    for (int kt = kt_start; kt <= qt; kt++) {
        const int k0 = kt * BK;
        __syncthreads(); // protect Ks/Vs/Ps from previous iteration's readers

        // ---- load K and V tiles ----
        #pragma unroll
        for (int i = 0; i < 4; i++) {
            int idx = tid + i * 256;
            int r   = idx >> 4;
            int c4  = idx & 15;
            *(float4*)(Ks + r * STRIDE + c4 * 4) =
                *(const float4*)(kp + (size_t)(k0 + r) * H_ * C_ + c4 * 4);
            *(float4*)(Vs + r * STRIDE + c4 * 4) =
                *(const float4*)(vp + (size_t)(k0 + r) * H_ * C_ + c4 * 4);
        }
        if (tid < BK) mks[tid] = mb[k0 + tid];
        __syncthreads();

        // ---- S = Q @ K^T  (64x64x64, 4x4 per thread, float4 smem reads) ----
        float acc[4][4];
        #pragma unroll
        for (int i = 0; i < 4; i++)
            #pragma unroll
            for (int j = 0; j < 4; j++) acc[i][j] = 0.f;

        #pragma unroll
        for (int kk = 0; kk < C_; kk += 4) {
            float4 a4[4], b4[4];
            #pragma unroll
            for (int i = 0; i < 4; i++)
                a4[i] = *(float4*)(Qs + (ty + 16 * i) * STRIDE + kk);
            #pragma unroll
            for (int j = 0; j < 4; j++)
                b4[j] = *(float4*)(Ks + (tx + 16 * j) * STRIDE + kk);
            #pragma unroll
            for (int i = 0; i < 4; i++)
                #pragma unroll
                for (int j = 0; j < 4; j++)
                    acc[i][j] += a4[i].x * b4[j].x + a4[i].y * b4[j].y
                               + a4[i].z * b4[j].z + a4[i].w * b4[j].w;
        }

        int mkv[4];
        #pragma unroll
        for (int j = 0; j < 4; j++) mkv[j] = mks[tx + 16 * j];

        // ---- mask + bias + online softmax, write P to smem ----
        #pragma unroll
        for (int i = 0; i < 4; i++) {
            const int qrow = q0 + ty + 16 * i;
            const float* brow = bp + (size_t)qrow * SEQ + k0;
            float val[4];
            bool  okf[4];
            float rm = -1e30f;
            #pragma unroll
            for (int j = 0; j < 4; j++) {
                const int kcol = k0 + tx + 16 * j;
                const bool ok = (kcol <= qrow) && (mkv[j] == mq[i]);
                okf[j] = ok;
                float bv = ok ? brow[tx + 16 * j] : 0.f;  // predicated LDG
                val[j] = ok ? (acc[i][j] * SM_SCALE + bv) : -1e30f;
                rm = fmaxf(rm, val[j]);
            }
            #pragma unroll
            for (int off = 8; off; off >>= 1)
                rm = fmaxf(rm, __shfl_xor_sync(0xffffffffu, rm, off, 16));

            const float mnew  = fmaxf(mi[i], rm);
            const float alpha = __expf(mi[i] - mnew);   // 1 if both -1e30 (o,l are 0)
            mi[i] = mnew;

            float rsum = 0.f;
            #pragma unroll
            for (int j = 0; j < 4; j++) {
                float p = okf[j] ? __expf(val[j] - mnew) : 0.f;
                val[j] = p;
                rsum += p;
            }
            #pragma unroll
            for (int off = 8; off; off >>= 1)
                rsum += __shfl_xor_sync(0xffffffffu, rsum, off, 16);

            li[i] = li[i] * alpha + rsum;
            #pragma unroll
            for (int j = 0; j < 4; j++) {
                o[i][j] *= alpha;
                Ps[(ty + 16 * i) * STRIDE + tx + 16 * j] = val[j];
            }
        }
        __syncthreads();

        // ---- O += P @ V  (64x64x64) ----
        #pragma unroll
        for (int kk = 0; kk < BK; kk += 4) {
            float4 a4[4];
            #pragma unroll
            for (int i = 0; i < 4; i++)
                a4[i] = *(float4*)(Ps + (ty + 16 * i) * STRIDE + kk);
            float bv[4][4];
            #pragma unroll
            for (int t = 0; t < 4; t++)
                #pragma unroll
                for (int j = 0; j < 4; j++)
                    bv[t][j] = Vs[(kk + t) * STRIDE + tx + 16 * j];
            #pragma unroll
            for (int i = 0; i < 4; i++)
                #pragma unroll
                for (int j = 0; j < 4; j++)
                    o[i][j] += a4[i].x * bv[0][j] + a4[i].y * bv[1][j]
                             + a4[i].z * bv[2][j] + a4[i].w * bv[3][j];
        }
    }

    // ---- normalize and store (every row has at least its diagonal -> li > 0) ----
    #pragma unroll
    for (int i = 0; i < 4; i++) {
        const int qrow = q0 + ty + 16 * i;
        const float inv = 1.f / li[i];
        float* op = out + ((size_t)(b * SEQ + qrow) * H_ + h) * C_;
        #pragma unroll
        for (int j = 0; j < 4; j++)
            op[tx + 16 * j] = o[i][j] * inv;
    }
}

constexpr int SMEM_BYTES = (4 * BQ * STRIDE) * (int)sizeof(float) + BK * (int)sizeof(int);

} // namespace

extern "C" void kernel_launch(void* const* d_in, const int* in_sizes, int n_in,
                              void* d_out, int out_size)
{
    (void)in_sizes; (void)n_in; (void)out_size;
    const float* q    = (const float*)d_in[0];
    const float* k    = (const float*)d_in[1];
    const float* v    = (const float*)d_in[2];
    const float* bias = (const float*)d_in[3];
    const int*   m    = (const int*)d_in[4];
    float* out = (float*)d_out;

    cudaFuncSetAttribute(attn_fa_kernel,
                         cudaFuncAttributeMaxDynamicSharedMemorySize, SMEM_BYTES);

    dim3 grid(SEQ / BQ, H_, B_);  // (32, 16, 2)
    attn_fa_kernel<<<grid, 256, SMEM_BYTES>>>(q, k, v, bias, m, out);
}

// round 2
// speedup vs baseline: 2.4677x; 2.4677x over previous
#include <cuda_runtime.h>
#include <stdint.h>
#include <math.h>

// q,k,v: (B=2, S=2048, H=16, C=64) f32 ; bias: (B,H,S,S) f32 ; m: (B,S) i32 sorted
// out: (B,S,H,C) f32
namespace {

constexpr int SEQ = 2048;
constexpr int H_  = 16;
constexpr int C_  = 64;
constexpr int BQ  = 64;
constexpr int BK  = 64;
constexpr int ST  = 68;            // smem row stride in 32-bit words
constexpr float SM_SCALE = 0.125f; // 1/sqrt(64)

__device__ __forceinline__ uint32_t f2tf(float x) {
    uint32_t y;
    asm("cvt.rna.tf32.f32 %0, %1;" : "=r"(y) : "f"(x));
    return y;
}

__device__ __forceinline__ void mma8(float* d, const uint32_t* a, const uint32_t* b) {
    asm volatile(
        "mma.sync.aligned.m16n8k8.row.col.f32.tf32.tf32.f32 "
        "{%0,%1,%2,%3}, {%4,%5,%6,%7}, {%8,%9}, {%0,%1,%2,%3};"
        : "+f"(d[0]), "+f"(d[1]), "+f"(d[2]), "+f"(d[3])
        : "r"(a[0]), "r"(a[1]), "r"(a[2]), "r"(a[3]), "r"(b[0]), "r"(b[1]));
}

__global__ void __launch_bounds__(128)
attn_mma(const float* __restrict__ q, const float* __restrict__ k,
         const float* __restrict__ v, const float* __restrict__ bias,
         const int* __restrict__ m, float* __restrict__ out)
{
    extern __shared__ float smem[];
    float* Qs = smem;                 // BQ x ST (tf32 bits)
    float* Ks = Qs + BQ * ST;         // BK x ST (tf32 bits)
    float* Vs = Ks + BK * ST;         // BK x ST (tf32 bits)
    float* Ps = Vs + BK * ST;         // BQ x ST (tf32 bits), per-warp private rows

    // heavy q-tiles first for tail balance
    const int qt = (int)gridDim.x - 1 - (int)blockIdx.x;
    const int h  = blockIdx.y;
    const int b  = blockIdx.z;
    const int q0 = qt * BQ;

    const int tid  = threadIdx.x;
    const int w    = tid >> 5;
    const int lane = tid & 31;
    const int g    = lane >> 2;   // group id 0..7
    const int tig  = lane & 3;    // thread in group 0..3
    const int r0   = 16 * w + g;  // my rows within the q-tile
    const int r1   = r0 + 8;
    const int qrow0 = q0 + r0;
    const int qrow1 = q0 + r1;

    const size_t qkv_base = ((size_t)(b * SEQ) * H_ + h) * C_;
    const float* qp = q + qkv_base + (size_t)q0 * H_ * C_;
    const float* kp = k + qkv_base;
    const float* vp = v + qkv_base;
    const float* bp = bias + ((size_t)(b * H_ + h)) * SEQ * SEQ;
    const int*   mb = m + b * SEQ;

    // ---- load Q tile, convert to tf32 once ----
    #pragma unroll
    for (int i = 0; i < 8; i++) {
        int idx = tid + i * 128;
        int r = idx >> 4, c4 = idx & 15;
        float4 t = *(const float4*)(qp + (size_t)r * H_ * C_ + c4 * 4);
        uint4 u = { f2tf(t.x), f2tf(t.y), f2tf(t.z), f2tf(t.w) };
        *(uint4*)(Qs + r * ST + c4 * 4) = u;
    }

    // ---- segment bounds: m sorted => mask(q,k) = (k >= lower_bound(m[q])) && (k <= q)
    const int seg0 = mb[qrow0];
    const int seg1 = mb[qrow1];
    const int segt = mb[q0];
    auto lbound = [&](int key) {
        int lo = 0, hi = q0 + BQ;
        while (lo < hi) { int mid = (lo + hi) >> 1; if (mb[mid] < key) lo = mid + 1; else hi = mid; }
        return lo;
    };
    const int lo0 = lbound(seg0);
    const int lo1 = lbound(seg1);
    const int kt_start = lbound(segt) >> 6;   // uniform across CTA

    float oa[8][4];
    #pragma unroll
    for (int nt = 0; nt < 8; nt++) {
        #pragma unroll
        for (int i = 0; i < 4; i++) oa[nt][i] = 0.f;
    }
    float mi0 = -1e30f, mi1 = -1e30f, li0 = 0.f, li1 = 0.f;

    const uint32_t* Qu = (const uint32_t*)Qs;
    const uint32_t* Ku = (const uint32_t*)Ks;
    const uint32_t* Vu = (const uint32_t*)Vs;
    uint32_t*       Pu = (uint32_t*)Ps;

    for (int kt = kt_start; kt <= qt; kt++) {
        const int k0 = kt * BK;
        __syncthreads();  // protect Ks/Vs against previous iteration readers

        // ---- load K,V tiles, convert to tf32 ----
        #pragma unroll
        for (int i = 0; i < 8; i++) {
            int idx = tid + i * 128;
            int r = idx >> 4, c4 = idx & 15;
            float4 tk = *(const float4*)(kp + (size_t)(k0 + r) * H_ * C_ + c4 * 4);
            float4 tv = *(const float4*)(vp + (size_t)(k0 + r) * H_ * C_ + c4 * 4);
            uint4 uk = { f2tf(tk.x), f2tf(tk.y), f2tf(tk.z), f2tf(tk.w) };
            uint4 uv = { f2tf(tv.x), f2tf(tv.y), f2tf(tv.z), f2tf(tv.w) };
            *(uint4*)(Ks + r * ST + c4 * 4) = uk;
            *(uint4*)(Vs + r * ST + c4 * 4) = uv;
        }
        __syncthreads();

        // ---- bias prefetch (predicated float2, 32B sector aligned) ----
        float2 bf0[8], bf1[8];
        #pragma unroll
        for (int nt = 0; nt < 8; nt++) {
            const int kc = k0 + 8 * nt + 2 * tig;
            const bool a0 = (kc >= lo0) & (kc <= qrow0);
            const bool a1 = (kc + 1 >= lo0) & (kc + 1 <= qrow0);
            const bool c0 = (kc >= lo1) & (kc <= qrow1);
            const bool c1 = (kc + 1 >= lo1) & (kc + 1 <= qrow1);
            bf0[nt] = (a0 | a1) ? *(const float2*)(bp + (size_t)qrow0 * SEQ + kc)
                                : make_float2(0.f, 0.f);
            bf1[nt] = (c0 | c1) ? *(const float2*)(bp + (size_t)qrow1 * SEQ + kc)
                                : make_float2(0.f, 0.f);
        }

        // ---- S = Q K^T via tf32 MMA ----
        float sa[8][4];
        #pragma unroll
        for (int nt = 0; nt < 8; nt++) {
            #pragma unroll
            for (int i = 0; i < 4; i++) sa[nt][i] = 0.f;
        }
        #pragma unroll
        for (int s = 0; s < 8; s++) {
            uint32_t a[4];
            a[0] = Qu[r0 * ST + 8 * s + tig];
            a[1] = Qu[r1 * ST + 8 * s + tig];
            a[2] = Qu[r0 * ST + 8 * s + tig + 4];
            a[3] = Qu[r1 * ST + 8 * s + tig + 4];
            #pragma unroll
            for (int nt = 0; nt < 8; nt++) {
                uint32_t bb[2];
                bb[0] = Ku[(8 * nt + g) * ST + 8 * s + tig];
                bb[1] = Ku[(8 * nt + g) * ST + 8 * s + tig + 4];
                mma8(sa[nt], a, bb);
            }
        }

        // ---- mask + bias, row max ----
        float rm0 = -1e30f, rm1 = -1e30f;
        #pragma unroll
        for (int nt = 0; nt < 8; nt++) {
            const int kc = k0 + 8 * nt + 2 * tig;
            const bool o00 = (kc >= lo0) & (kc <= qrow0);
            const bool o01 = (kc + 1 >= lo0) & (kc + 1 <= qrow0);
            const bool o10 = (kc >= lo1) & (kc <= qrow1);
            const bool o11 = (kc + 1 >= lo1) & (kc + 1 <= qrow1);
            sa[nt][0] = o00 ? fmaf(sa[nt][0], SM_SCALE, bf0[nt].x) : -1e30f;
            sa[nt][1] = o01 ? fmaf(sa[nt][1], SM_SCALE, bf0[nt].y) : -1e30f;
            sa[nt][2] = o10 ? fmaf(sa[nt][2], SM_SCALE, bf1[nt].x) : -1e30f;
            sa[nt][3] = o11 ? fmaf(sa[nt][3], SM_SCALE, bf1[nt].y) : -1e30f;
            rm0 = fmaxf(rm0, fmaxf(sa[nt][0], sa[nt][1]));
            rm1 = fmaxf(rm1, fmaxf(sa[nt][2], sa[nt][3]));
        }
        rm0 = fmaxf(rm0, __shfl_xor_sync(0xffffffffu, rm0, 1));
        rm0 = fmaxf(rm0, __shfl_xor_sync(0xffffffffu, rm0, 2));
        rm1 = fmaxf(rm1, __shfl_xor_sync(0xffffffffu, rm1, 1));
        rm1 = fmaxf(rm1, __shfl_xor_sync(0xffffffffu, rm1, 2));

        const float mn0 = fmaxf(mi0, rm0);
        const float mn1 = fmaxf(mi1, rm1);
        const float al0 = __expf(mi0 - mn0);
        const float al1 = __expf(mi1 - mn1);
        mi0 = mn0; mi1 = mn1;

        // ---- exp + P store (tf32). Masked entries: exp(-1e30 - mn) == 0 when mn
        // finite; the all-masked-so-far case produces junk that alpha==0 kills at
        // the first live tile, so no extra predicate needed.
        float rs0 = 0.f, rs1 = 0.f;
        #pragma unroll
        for (int nt = 0; nt < 8; nt++) {
            float p00 = __expf(sa[nt][0] - mn0);
            float p01 = __expf(sa[nt][1] - mn0);
            float p10 = __expf(sa[nt][2] - mn1);
            float p11 = __expf(sa[nt][3] - mn1);
            rs0 += p00 + p01;
            rs1 += p10 + p11;
            const int cc = 8 * nt + 2 * tig;
            Pu[r0 * ST + cc]     = f2tf(p00);
            Pu[r0 * ST + cc + 1] = f2tf(p01);
            Pu[r1 * ST + cc]     = f2tf(p10);
            Pu[r1 * ST + cc + 1] = f2tf(p11);
        }
        rs0 += __shfl_xor_sync(0xffffffffu, rs0, 1);
        rs0 += __shfl_xor_sync(0xffffffffu, rs0, 2);
        rs1 += __shfl_xor_sync(0xffffffffu, rs1, 1);
        rs1 += __shfl_xor_sync(0xffffffffu, rs1, 2);
        li0 = li0 * al0 + rs0;
        li1 = li1 * al1 + rs1;

        #pragma unroll
        for (int nt = 0; nt < 8; nt++) {
            oa[nt][0] *= al0; oa[nt][1] *= al0;
            oa[nt][2] *= al1; oa[nt][3] *= al1;
        }

        __syncwarp();  // P rows 16w..16w+15 written & read only by warp w

        // ---- O += P V via tf32 MMA ----
        #pragma unroll
        for (int s = 0; s < 8; s++) {
            uint32_t a[4];
            a[0] = Pu[r0 * ST + 8 * s + tig];
            a[1] = Pu[r1 * ST + 8 * s + tig];
            a[2] = Pu[r0 * ST + 8 * s + tig + 4];
            a[3] = Pu[r1 * ST + 8 * s + tig + 4];
            #pragma unroll
            for (int nt = 0; nt < 8; nt++) {
                uint32_t bb[2];
                bb[0] = Vu[(8 * s + tig) * ST + 8 * nt + g];
                bb[1] = Vu[(8 * s + tig + 4) * ST + 8 * nt + g];
                mma8(oa[nt], a, bb);
            }
        }
    }

    // ---- normalize + store ----
    const float inv0 = 1.f / li0;
    const float inv1 = 1.f / li1;
    float* op0 = out + ((size_t)(b * SEQ + qrow0) * H_ + h) * C_;
    float* op1 = out + ((size_t)(b * SEQ + qrow1) * H_ + h) * C_;
    #pragma unroll
    for (int nt = 0; nt < 8; nt++) {
        const int cc = 8 * nt + 2 * tig;
        *(float2*)(op0 + cc) = make_float2(oa[nt][0] * inv0, oa[nt][1] * inv0);
        *(float2*)(op1 + cc) = make_float2(oa[nt][2] * inv1, oa[nt][3] * inv1);
    }
}

constexpr int SMEM_BYTES = 4 * BQ * ST * (int)sizeof(float);  // 69,632 B

} // namespace

extern "C" void kernel_launch(void* const* d_in, const int* in_sizes, int n_in,
                              void* d_out, int out_size)
{
    (void)in_sizes; (void)n_in; (void)out_size;
    const float* q    = (const float*)d_in[0];
    const float* k    = (const float*)d_in[1];
    const float* v    = (const float*)d_in[2];
    const float* bias = (const float*)d_in[3];
    const int*   m    = (const int*)d_in[4];
    float* out = (float*)d_out;

    cudaFuncSetAttribute(attn_mma,
                         cudaFuncAttributeMaxDynamicSharedMemorySize, SMEM_BYTES);

    dim3 grid(SEQ / BQ, H_, 2);  // (32, 16, 2)
    attn_mma<<<grid, 128, SMEM_BYTES>>>(q, k, v, bias, m, out);
}